// round 10
// baseline (speedup 1.0000x reference)
#include <cuda_runtime.h>
#include <cuda_bf16.h>
#include <cstdint>
#include <cstddef>

#define BATCH 64
#define HW    256
#define CH    1024
#define NTOK  256
#define TC    768
#define FD    512
#define MROWS (BATCH*HW)   // 16384

// ------------------------------ scratch (device globals; no allocs) ---------
__device__ __align__(256) __nv_bfloat16 g_x1h[(size_t)MROWS*CH], g_x1l[(size_t)MROWS*CH];
__device__ __align__(256) __nv_bfloat16 g_x2h[(size_t)MROWS*TC], g_x2l[(size_t)MROWS*TC];
__device__ __align__(256) __nv_bfloat16 g_wqh[(size_t)FD*CH],  g_wql[(size_t)FD*CH];
__device__ __align__(256) __nv_bfloat16 g_wkh[(size_t)FD*TC],  g_wkl[(size_t)FD*TC];
__device__ __align__(256) __nv_bfloat16 g_wvh[(size_t)TC*CH],  g_wvl[(size_t)TC*CH];   // straight split of Wv [768,1024]
__device__ __align__(256) __nv_bfloat16 g_woh[(size_t)CH*CH],  g_wol[(size_t)CH*CH];   // Wo^T [f,c]
__device__ __align__(256) __nv_bfloat16 g_Qh[(size_t)MROWS*FD], g_Ql[(size_t)MROWS*FD];
__device__ __align__(256) __nv_bfloat16 g_Kh[(size_t)MROWS*FD], g_Kl[(size_t)MROWS*FD];
__device__ __align__(256) float         g_Wvo[(size_t)TC*CH];                          // Wv@Wo fp32
__device__ __align__(256) float         g_bvo[CH];                                     // bv@Wo
__device__ __align__(256) __nv_bfloat16 g_Wvoth[(size_t)CH*TC], g_Wvotl[(size_t)CH*TC];// (Wv@Wo)^T hi/lo
__device__ __align__(256) float         g_VW[(size_t)MROWS*CH];                        // x2@Wvo fp32
__device__ __align__(256) __nv_bfloat16 g_VWth[(size_t)MROWS*CH], g_VWtl[(size_t)MROWS*CH]; // [b][CH][NTOK]
__device__ __align__(256) float         g_S [(size_t)MROWS*NTOK];
__device__ __align__(256) __nv_bfloat16 g_bh[(size_t)MROWS*NTOK], g_bl[(size_t)MROWS*NTOK];

// ------------------------------ PTX helpers (all portable, sm_80+) ----------
__device__ __forceinline__ uint32_t smem_u32(const void* p) {
    uint32_t a;
    asm("{ .reg .u64 t; cvta.to.shared.u64 t, %1; cvt.u32.u64 %0, t; }" : "=r"(a) : "l"(p));
    return a;
}
#define CP_ASYNC16(dst, src) \
    asm volatile("cp.async.cg.shared.global [%0], [%1], 16;" :: "r"(dst), "l"(src))
#define CP_COMMIT() asm volatile("cp.async.commit_group;" ::: "memory")
#define CP_WAIT1()  asm volatile("cp.async.wait_group 1;" ::: "memory")
#define CP_WAIT0()  asm volatile("cp.async.wait_group 0;" ::: "memory")

#define LDMX4(r, addr)                                                      \
    asm volatile("ldmatrix.sync.aligned.m8n8.x4.shared.b16 {%0,%1,%2,%3}, [%4];" \
        : "=r"((r)[0]), "=r"((r)[1]), "=r"((r)[2]), "=r"((r)[3]) : "r"(addr))

#define MMA16816(c, a, b)                                                   \
    asm volatile("mma.sync.aligned.m16n8k16.row.col.f32.bf16.bf16.f32 "     \
        "{%0,%1,%2,%3}, {%4,%5,%6,%7}, {%8,%9}, {%0,%1,%2,%3};"             \
        : "+f"((c)[0]), "+f"((c)[1]), "+f"((c)[2]), "+f"((c)[3])            \
        : "r"((a)[0]), "r"((a)[1]), "r"((a)[2]), "r"((a)[3]),               \
          "r"((b)[0]), "r"((b)[1]))

// ------------------------------ GEMM (R7 config, unchanged) -----------------
#define STG_BYTES 32768
#define SMEM_BYTES (2*STG_BYTES)

__device__ __forceinline__ void cp_tile2(
    const __nv_bfloat16* __restrict__ gh, const __nv_bfloat16* __restrict__ gl,
    int row0, int kof, int pitch, uint32_t sdst, int tid)
{
#pragma unroll
    for (int i = 0; i < 2; ++i) {
        int u = tid + i * 256;
        int row = u >> 2;
        int c4 = u & 3;
        {
            int c = c4;
            uint32_t dst = sdst + row * 128 + ((c ^ (row & 7)) << 4);
            const void* src = gh + (size_t)(row0 + row) * pitch + kof + c4 * 8;
            CP_ASYNC16(dst, src);
        }
        {
            int c = c4 + 4;
            uint32_t dst = sdst + row * 128 + ((c ^ (row & 7)) << 4);
            const void* src = gl + (size_t)(row0 + row) * pitch + kof + c4 * 8;
            CP_ASYNC16(dst, src);
        }
    }
}

template <int MODE>
__global__ __launch_bounds__(256, 2) void mma_gemm(
    const __nv_bfloat16* __restrict__ Ah, const __nv_bfloat16* __restrict__ Al,
    const __nv_bfloat16* __restrict__ Bh, const __nv_bfloat16* __restrict__ Bl,
    const float* __restrict__ bias,
    float* __restrict__ Cf, __nv_bfloat16* __restrict__ Chi, __nv_bfloat16* __restrict__ Clo,
    int K, int ldc, size_t sA, size_t sB, size_t sC)
{
    extern __shared__ char smem[];
    const uint32_t sbase = smem_u32(smem);
    const int tid  = threadIdx.x;
    const int lane = tid & 31;
    const int wid  = tid >> 5;
    const int mw   = wid & 3;
    const int nw   = wid >> 2;
    const int m0 = blockIdx.y * 128;
    const int n0 = blockIdx.x * 128;
    const size_t z = blockIdx.z;
    Ah += z * sA; Al += z * sA;
    Bh += z * sB; Bl += z * sB;

    float c[2][8][4];
#pragma unroll
    for (int i = 0; i < 2; ++i)
#pragma unroll
        for (int j = 0; j < 8; ++j)
#pragma unroll
            for (int e = 0; e < 4; ++e) c[i][j][e] = 0.f;

    const int KS = K >> 5;

    cp_tile2(Ah, Al, m0, 0, K, sbase + 0,     tid);
    cp_tile2(Bh, Bl, n0, 0, K, sbase + 16384, tid);
    CP_COMMIT();

    const int a_r = lane & 15;
    const int a_c = lane >> 4;
    const int b_r = ((lane >> 4) << 3) + (lane & 7);
    const int b_c = (lane >> 3) & 1;

    for (int s = 0; s < KS; ++s) {
        const uint32_t sb = sbase + (s & 1) * STG_BYTES;
        if (s + 1 < KS) {
            const uint32_t nb = sbase + ((s + 1) & 1) * STG_BYTES;
            const int kof = (s + 1) * 32;
            cp_tile2(Ah, Al, m0, kof, K, nb + 0,     tid);
            cp_tile2(Bh, Bl, n0, kof, K, nb + 16384, tid);
            CP_COMMIT();
            CP_WAIT1();
        } else {
            CP_WAIT0();
        }
        __syncthreads();

#pragma unroll
        for (int kk = 0; kk < 2; ++kk) {
            uint32_t a_h[2][4], a_l[2][4];
#pragma unroll
            for (int mi = 0; mi < 2; ++mi) {
                const int row = mw * 32 + mi * 16 + a_r;
                const int ch = kk * 2 + a_c;
                const uint32_t base = sb + row * 128;
                LDMX4(a_h[mi], base + ((ch       ^ (row & 7)) << 4));
                LDMX4(a_l[mi], base + (((ch + 4) ^ (row & 7)) << 4));
            }
#pragma unroll
            for (int np = 0; np < 4; ++np) {
                const int n = nw * 64 + np * 16 + b_r;
                const int ch = kk * 2 + b_c;
                const uint32_t base = sb + 16384 + n * 128;
                uint32_t bhf[4], blf[4];
                LDMX4(bhf, base + ((ch       ^ (n & 7)) << 4));
                LDMX4(blf, base + (((ch + 4) ^ (n & 7)) << 4));
#pragma unroll
                for (int mi = 0; mi < 2; ++mi) {
                    MMA16816(c[mi][2*np+0], a_h[mi], &bhf[0]);
                    MMA16816(c[mi][2*np+0], a_h[mi], &blf[0]);
                    MMA16816(c[mi][2*np+0], a_l[mi], &bhf[0]);
                    MMA16816(c[mi][2*np+1], a_h[mi], &bhf[2]);
                    MMA16816(c[mi][2*np+1], a_h[mi], &blf[2]);
                    MMA16816(c[mi][2*np+1], a_l[mi], &bhf[2]);
                }
            }
        }
        __syncthreads();
    }

    const int r_base = m0 + mw * 32 + (lane >> 2);
    const int c_base = n0 + nw * 64 + (lane & 3) * 2;
#pragma unroll
    for (int mi = 0; mi < 2; ++mi) {
#pragma unroll
        for (int hf = 0; hf < 2; ++hf) {
            const size_t row = (size_t)(r_base + mi * 16 + hf * 8);
#pragma unroll
            for (int nj = 0; nj < 8; ++nj) {
                const int col = c_base + nj * 8;
                float v0 = c[mi][nj][hf * 2 + 0];
                float v1 = c[mi][nj][hf * 2 + 1];
                if (bias) { v0 += __ldg(&bias[col]); v1 += __ldg(&bias[col + 1]); }
                if (MODE == 0) {
                    float2* dst = (float2*)(Cf + z * sC + row * ldc + col);
                    *dst = make_float2(v0, v1);
                } else {
                    __nv_bfloat16 h0 = __float2bfloat16_rn(v0);
                    __nv_bfloat16 h1 = __float2bfloat16_rn(v1);
                    __nv_bfloat16 l0 = __float2bfloat16_rn(v0 - __bfloat162float(h0));
                    __nv_bfloat16 l1 = __float2bfloat16_rn(v1 - __bfloat162float(h1));
                    uint32_t hw = (uint32_t)__bfloat16_as_ushort(h0) | ((uint32_t)__bfloat16_as_ushort(h1) << 16);
                    uint32_t lw = (uint32_t)__bfloat16_as_ushort(l0) | ((uint32_t)__bfloat16_as_ushort(l1) << 16);
                    *(uint32_t*)(Chi + z * sC + row * ldc + col) = hw;
                    *(uint32_t*)(Clo + z * sC + row * ldc + col) = lw;
                }
            }
        }
    }
}

// ------------------------------ aux kernels ---------------------------------
__global__ __launch_bounds__(256) void split_kernel(
    const float4* __restrict__ src, __nv_bfloat16* __restrict__ dh,
    __nv_bfloat16* __restrict__ dl, int n4)
{
    int i = blockIdx.x * 256 + threadIdx.x;
    if (i >= n4) return;
    float4 v = src[i];
    float fv[4] = {v.x, v.y, v.z, v.w};
    uint32_t hw[2], lw[2];
#pragma unroll
    for (int p = 0; p < 2; ++p) {
        __nv_bfloat16 h0 = __float2bfloat16_rn(fv[2*p]);
        __nv_bfloat16 h1 = __float2bfloat16_rn(fv[2*p+1]);
        __nv_bfloat16 l0 = __float2bfloat16_rn(fv[2*p]   - __bfloat162float(h0));
        __nv_bfloat16 l1 = __float2bfloat16_rn(fv[2*p+1] - __bfloat162float(h1));
        hw[p] = (uint32_t)__bfloat16_as_ushort(h0) | ((uint32_t)__bfloat16_as_ushort(h1) << 16);
        lw[p] = (uint32_t)__bfloat16_as_ushort(l0) | ((uint32_t)__bfloat16_as_ushort(l1) << 16);
    }
    ((uint2*)dh)[i] = make_uint2(hw[0], hw[1]);
    ((uint2*)dl)[i] = make_uint2(lw[0], lw[1]);
}

// dst[c][r] = split(src[r][c]); src [R,C] fp32, dst [C,R] bf16 hi/lo, batched.
__global__ __launch_bounds__(256) void tsplit_kernel(
    const float* __restrict__ src, __nv_bfloat16* __restrict__ dh,
    __nv_bfloat16* __restrict__ dl, int R, int C, size_t sS, size_t sD)
{
    __shared__ float t[32][33];
    const size_t z = blockIdx.z;
    src += z * sS; dh += z * sD; dl += z * sD;
    const int c0 = blockIdx.x * 32, r0 = blockIdx.y * 32;
    const int tx = threadIdx.x, ty = threadIdx.y;
#pragma unroll
    for (int k = 0; k < 4; ++k)
        t[ty + 8*k][tx] = src[(size_t)(r0 + ty + 8*k) * C + c0 + tx];
    __syncthreads();
#pragma unroll
    for (int k = 0; k < 4; ++k) {
        float f = t[tx][ty + 8*k];
        __nv_bfloat16 h = __float2bfloat16_rn(f);
        size_t o = (size_t)(c0 + ty + 8*k) * R + r0 + tx;
        dh[o] = h;
        dl[o] = __float2bfloat16_rn(f - __bfloat162float(h));
    }
}

// bvo[f] = sum_c bv[c] * Wo[c][f]
__global__ __launch_bounds__(256) void bvo_kernel(
    const float* __restrict__ bv, const float* __restrict__ wo,
    float* __restrict__ bvo)
{
    int f = blockIdx.x * 256 + threadIdx.x;
    float s = 0.f;
    for (int c = 0; c < CH; ++c) s = fmaf(bv[c], wo[(size_t)c * CH + f], s);
    bvo[f] = s;
}

__global__ __launch_bounds__(256) void softmax_mask_split_kernel(
    const float* __restrict__ S, const float* __restrict__ masks,
    float* __restrict__ beta, __nv_bfloat16* __restrict__ bh,
    __nv_bfloat16* __restrict__ bl)
{
    const int row = blockIdx.x;
    const int b = row >> 8;
    const int n = threadIdx.x;
    __shared__ float red[256];

    const size_t idx = (size_t)row * NTOK + n;
    float v = S[idx];
    red[n] = v;
    __syncthreads();
#pragma unroll
    for (int s = 128; s > 0; s >>= 1) {
        if (n < s) red[n] = fmaxf(red[n], red[n + s]);
        __syncthreads();
    }
    const float mx = red[0];
    __syncthreads();
    const float e = expf(v - mx);
    red[n] = e;
    __syncthreads();
#pragma unroll
    for (int s = 128; s > 0; s >>= 1) {
        if (n < s) red[n] += red[n + s];
        __syncthreads();
    }
    const float r = e / red[0] * masks[b * NTOK + n];
    beta[idx] = r;
    __nv_bfloat16 h = __float2bfloat16_rn(r);
    bh[idx] = h;
    bl[idx] = __float2bfloat16_rn(r - __bfloat162float(h));
}

// ------------------------------ host ----------------------------------------
extern "C" void kernel_launch(void* const* d_in, const int* in_sizes, int n_in,
                              void* d_out, int out_size) {
    const float* x1    = (const float*)d_in[0];
    const float* x2    = (const float*)d_in[1];
    const float* masks = (const float*)d_in[2];
    const float* wq    = (const float*)d_in[3];
    const float* bq    = (const float*)d_in[4];
    const float* wk    = (const float*)d_in[5];
    const float* bk    = (const float*)d_in[6];
    const float* wv    = (const float*)d_in[7];
    const float* bv    = (const float*)d_in[8];
    const float* wo    = (const float*)d_in[9];
    const float* bo    = (const float*)d_in[10];

    float* out      = (float*)d_out;
    float* o_out    = out;
    float* beta_out = out + (size_t)MROWS * CH;

    __nv_bfloat16 *x1h, *x1l, *x2h, *x2l, *wqh, *wql, *wkh, *wkl, *wvh, *wvl,
                  *woh, *wol, *Qh, *Ql, *Kh, *Kl, *Wvoth, *Wvotl, *VWth, *VWtl, *bh, *bl;
    float *Wvo, *bvo, *VWf, *Sf;
    cudaGetSymbolAddress((void**)&x1h, g_x1h); cudaGetSymbolAddress((void**)&x1l, g_x1l);
    cudaGetSymbolAddress((void**)&x2h, g_x2h); cudaGetSymbolAddress((void**)&x2l, g_x2l);
    cudaGetSymbolAddress((void**)&wqh, g_wqh); cudaGetSymbolAddress((void**)&wql, g_wql);
    cudaGetSymbolAddress((void**)&wkh, g_wkh); cudaGetSymbolAddress((void**)&wkl, g_wkl);
    cudaGetSymbolAddress((void**)&wvh, g_wvh); cudaGetSymbolAddress((void**)&wvl, g_wvl);
    cudaGetSymbolAddress((void**)&woh, g_woh); cudaGetSymbolAddress((void**)&wol, g_wol);
    cudaGetSymbolAddress((void**)&Qh,  g_Qh);  cudaGetSymbolAddress((void**)&Ql,  g_Ql);
    cudaGetSymbolAddress((void**)&Kh,  g_Kh);  cudaGetSymbolAddress((void**)&Kl,  g_Kl);
    cudaGetSymbolAddress((void**)&Wvo, g_Wvo); cudaGetSymbolAddress((void**)&bvo, g_bvo);
    cudaGetSymbolAddress((void**)&Wvoth, g_Wvoth); cudaGetSymbolAddress((void**)&Wvotl, g_Wvotl);
    cudaGetSymbolAddress((void**)&VWf, g_VW);
    cudaGetSymbolAddress((void**)&VWth, g_VWth); cudaGetSymbolAddress((void**)&VWtl, g_VWtl);
    cudaGetSymbolAddress((void**)&Sf,  g_S);
    cudaGetSymbolAddress((void**)&bh,  g_bh);  cudaGetSymbolAddress((void**)&bl,  g_bl);

    cudaFuncSetAttribute(mma_gemm<0>, cudaFuncAttributeMaxDynamicSharedMemorySize, SMEM_BYTES);
    cudaFuncSetAttribute(mma_gemm<1>, cudaFuncAttributeMaxDynamicSharedMemorySize, SMEM_BYTES);

    // one-time host-side stream/event setup (no device memory involved)
    static cudaStream_t sA = nullptr, sC = nullptr;
    static cudaEvent_t evRoot = nullptr, evX2 = nullptr, evQ = nullptr, evVW = nullptr;
    if (!sA) {
        cudaStreamCreateWithFlags(&sA, cudaStreamNonBlocking);
        cudaStreamCreateWithFlags(&sC, cudaStreamNonBlocking);
        cudaEventCreateWithFlags(&evRoot, cudaEventDisableTiming);
        cudaEventCreateWithFlags(&evX2,   cudaEventDisableTiming);
        cudaEventCreateWithFlags(&evQ,    cudaEventDisableTiming);
        cudaEventCreateWithFlags(&evVW,   cudaEventDisableTiming);
    }

    const dim3 T(256);
    const dim3 TT(32, 8);

    // fork from origin (default) stream
    cudaEventRecord(evRoot, 0);
    cudaStreamWaitEvent(sA, evRoot, 0);
    cudaStreamWaitEvent(sC, evRoot, 0);

    // ---- chain A (stream sA): x1 split -> Wq prep -> Q GEMM ----
    split_kernel<<<(MROWS*CH/4 + 255)/256, 256, 0, sA>>>((const float4*)x1, x1h, x1l, MROWS*CH/4);
    tsplit_kernel<<<dim3(FD/32, CH/32, 1), TT, 0, sA>>>(wq, wqh, wql, CH, FD, 0, 0);
    mma_gemm<1><<<dim3(FD/128, MROWS/128, 1), T, SMEM_BYTES, sA>>>(
        x1h, x1l, wqh, wql, bq, nullptr, Qh, Ql, CH, FD, 0, 0, 0);
    cudaEventRecord(evQ, sA);

    // ---- chain B (default): x2 split -> Wk prep -> K GEMM ----
    split_kernel<<<(MROWS*TC/4 + 255)/256, 256>>>((const float4*)x2, x2h, x2l, MROWS*TC/4);
    cudaEventRecord(evX2, 0);
    tsplit_kernel<<<dim3(FD/32, TC/32, 1), TT>>>(wk, wkh, wkl, TC, FD, 0, 0);
    mma_gemm<1><<<dim3(FD/128, MROWS/128, 1), T, SMEM_BYTES>>>(
        x2h, x2l, wkh, wkl, bk, nullptr, Kh, Kl, TC, FD, 0, 0, 0);

    // ---- chain C (stream sC): Wvo fold -> VW GEMM -> VW transpose ----
    split_kernel<<<(TC*CH/4 + 255)/256, 256, 0, sC>>>((const float4*)wv, wvh, wvl, TC*CH/4);
    tsplit_kernel<<<dim3(CH/32, CH/32, 1), TT, 0, sC>>>(wo, woh, wol, CH, CH, 0, 0);
    bvo_kernel<<<CH/256, 256, 0, sC>>>(bv, wo, bvo);
    mma_gemm<0><<<dim3(CH/128, TC/128, 1), T, SMEM_BYTES, sC>>>(
        wvh, wvl, woh, wol, nullptr, Wvo, nullptr, nullptr, CH, CH, 0, 0, 0);
    tsplit_kernel<<<dim3(CH/32, TC/32, 1), TT, 0, sC>>>(Wvo, Wvoth, Wvotl, TC, CH, 0, 0);
    cudaStreamWaitEvent(sC, evX2, 0);       // VW GEMM reads x2 split from chain B
    mma_gemm<0><<<dim3(CH/128, MROWS/128, 1), T, SMEM_BYTES, sC>>>(
        x2h, x2l, Wvoth, Wvotl, bvo, VWf, nullptr, nullptr, TC, CH, 0, 0, 0);
    tsplit_kernel<<<dim3(CH/32, NTOK/32, BATCH), TT, 0, sC>>>(
        VWf, VWth, VWtl, NTOK, CH, (size_t)NTOK*CH, (size_t)NTOK*CH);
    cudaEventRecord(evVW, sC);

    // ---- join on default: S -> softmax -> o ----
    cudaStreamWaitEvent(0, evQ, 0);
    mma_gemm<0><<<dim3(NTOK/128, HW/128, BATCH), T, SMEM_BYTES>>>(
        Qh, Ql, Kh, Kl, nullptr, Sf, nullptr, nullptr, FD, NTOK,
        (size_t)HW*FD, (size_t)NTOK*FD, (size_t)HW*NTOK);

    softmax_mask_split_kernel<<<MROWS, 256>>>(Sf, masks, beta_out, bh, bl);

    cudaStreamWaitEvent(0, evVW, 0);
    mma_gemm<0><<<dim3(CH/128, HW/128, BATCH), T, SMEM_BYTES>>>(
        bh, bl, VWth, VWtl, bo, o_out, nullptr, nullptr, NTOK, CH,
        (size_t)HW*NTOK, (size_t)CH*NTOK, (size_t)HW*CH);
}

// round 11
// speedup vs baseline: 1.2171x; 1.2171x over previous
#include <cuda_runtime.h>
#include <cuda_bf16.h>
#include <cstdint>
#include <cstddef>

#define BATCH 64
#define HW    256
#define CH    1024
#define NTOK  256
#define TC    768
#define FD    512
#define MROWS (BATCH*HW)   // 16384

// ------------------------------ scratch (device globals; no allocs) ---------
__device__ __align__(256) __nv_bfloat16 g_x1h[(size_t)MROWS*CH], g_x1l[(size_t)MROWS*CH];
__device__ __align__(256) __nv_bfloat16 g_x2h[(size_t)MROWS*TC], g_x2l[(size_t)MROWS*TC];
__device__ __align__(256) __nv_bfloat16 g_wqh[(size_t)FD*CH],  g_wql[(size_t)FD*CH];
__device__ __align__(256) __nv_bfloat16 g_wkh[(size_t)FD*TC],  g_wkl[(size_t)FD*TC];
__device__ __align__(256) __nv_bfloat16 g_wvh[(size_t)TC*CH],  g_wvl[(size_t)TC*CH];   // split of Wv [768,1024]
__device__ __align__(256) __nv_bfloat16 g_woh[(size_t)CH*CH],  g_wol[(size_t)CH*CH];   // Wo^T [f,c]
__device__ __align__(256) __nv_bfloat16 g_Qh[(size_t)MROWS*FD], g_Ql[(size_t)MROWS*FD];
__device__ __align__(256) __nv_bfloat16 g_Kh[(size_t)MROWS*FD], g_Kl[(size_t)MROWS*FD];
__device__ __align__(256) float         g_bvo[CH];                                     // bv@Wo
__device__ __align__(256) __nv_bfloat16 g_Wvoth[(size_t)CH*TC], g_Wvotl[(size_t)CH*TC];// (Wv@Wo)^T hi/lo [1024,768]
__device__ __align__(256) __nv_bfloat16 g_VWth[(size_t)MROWS*CH], g_VWtl[(size_t)MROWS*CH]; // [b][CH][NTOK]
__device__ __align__(256) float         g_S [(size_t)MROWS*NTOK];
__device__ __align__(256) __nv_bfloat16 g_bh[(size_t)MROWS*NTOK], g_bl[(size_t)MROWS*NTOK];

// ------------------------------ PTX helpers (all portable, sm_80+) ----------
__device__ __forceinline__ uint32_t smem_u32(const void* p) {
    uint32_t a;
    asm("{ .reg .u64 t; cvta.to.shared.u64 t, %1; cvt.u32.u64 %0, t; }" : "=r"(a) : "l"(p));
    return a;
}
#define CP_ASYNC16(dst, src) \
    asm volatile("cp.async.cg.shared.global [%0], [%1], 16;" :: "r"(dst), "l"(src))
#define CP_COMMIT() asm volatile("cp.async.commit_group;" ::: "memory")
#define CP_WAIT1()  asm volatile("cp.async.wait_group 1;" ::: "memory")
#define CP_WAIT0()  asm volatile("cp.async.wait_group 0;" ::: "memory")

#define LDMX4(r, addr)                                                      \
    asm volatile("ldmatrix.sync.aligned.m8n8.x4.shared.b16 {%0,%1,%2,%3}, [%4];" \
        : "=r"((r)[0]), "=r"((r)[1]), "=r"((r)[2]), "=r"((r)[3]) : "r"(addr))

#define MMA16816(c, a, b)                                                   \
    asm volatile("mma.sync.aligned.m16n8k16.row.col.f32.bf16.bf16.f32 "     \
        "{%0,%1,%2,%3}, {%4,%5,%6,%7}, {%8,%9}, {%0,%1,%2,%3};"             \
        : "+f"((c)[0]), "+f"((c)[1]), "+f"((c)[2]), "+f"((c)[3])            \
        : "r"((a)[0]), "r"((a)[1]), "r"((a)[2]), "r"((a)[3]),               \
          "r"((b)[0]), "r"((b)[1]))

__device__ __forceinline__ void split2pack(float f0, float f1, uint32_t& hw, uint32_t& lw) {
    __nv_bfloat16 h0 = __float2bfloat16_rn(f0);
    __nv_bfloat16 h1 = __float2bfloat16_rn(f1);
    __nv_bfloat16 l0 = __float2bfloat16_rn(f0 - __bfloat162float(h0));
    __nv_bfloat16 l1 = __float2bfloat16_rn(f1 - __bfloat162float(h1));
    hw = (uint32_t)__bfloat16_as_ushort(h0) | ((uint32_t)__bfloat16_as_ushort(h1) << 16);
    lw = (uint32_t)__bfloat16_as_ushort(l0) | ((uint32_t)__bfloat16_as_ushort(l1) << 16);
}

// ------------------------------ GEMM (R7 mainloop) --------------------------
// C[M,N] (+bias) = (Ah+Al)[M,K] * (Bh+Bl)[N,K]^T via 3 bf16 MMAs.
// CTA tile 128x128, K-slab 32, 8 warps, cp.async double buffer, 64KB smem.
// MODE 0: fp32 row-major C.
// MODE 1: bf16 hi/lo row-major C.
// MODE 2: bf16 hi/lo TRANSPOSED C via smem (dst[n][m]); ldc = out pitch,
//         sC = batch stride, rbatch = source rows per batch (tile may not straddle).
#define STG_BYTES 32768
#define SMEM_BYTES (2*STG_BYTES)
#define SMEM_BYTES_T (128*129*4)   // 66048 for MODE 2 transpose stage

__device__ __forceinline__ void cp_tile2(
    const __nv_bfloat16* __restrict__ gh, const __nv_bfloat16* __restrict__ gl,
    int row0, int kof, int pitch, uint32_t sdst, int tid)
{
#pragma unroll
    for (int i = 0; i < 2; ++i) {
        int u = tid + i * 256;
        int row = u >> 2;
        int c4 = u & 3;
        {
            int c = c4;
            uint32_t dst = sdst + row * 128 + ((c ^ (row & 7)) << 4);
            const void* src = gh + (size_t)(row0 + row) * pitch + kof + c4 * 8;
            CP_ASYNC16(dst, src);
        }
        {
            int c = c4 + 4;
            uint32_t dst = sdst + row * 128 + ((c ^ (row & 7)) << 4);
            const void* src = gl + (size_t)(row0 + row) * pitch + kof + c4 * 8;
            CP_ASYNC16(dst, src);
        }
    }
}

template <int MODE>
__global__ __launch_bounds__(256, 2) void mma_gemm(
    const __nv_bfloat16* __restrict__ Ah, const __nv_bfloat16* __restrict__ Al,
    const __nv_bfloat16* __restrict__ Bh, const __nv_bfloat16* __restrict__ Bl,
    const float* __restrict__ bias,
    float* __restrict__ Cf, __nv_bfloat16* __restrict__ Chi, __nv_bfloat16* __restrict__ Clo,
    int K, int ldc, size_t sA, size_t sB, size_t sC, int rbatch)
{
    extern __shared__ char smem[];
    const uint32_t sbase = smem_u32(smem);
    const int tid  = threadIdx.x;
    const int lane = tid & 31;
    const int wid  = tid >> 5;
    const int mw   = wid & 3;
    const int nw   = wid >> 2;
    const int m0 = blockIdx.y * 128;
    const int n0 = blockIdx.x * 128;
    const size_t z = blockIdx.z;
    Ah += z * sA; Al += z * sA;
    Bh += z * sB; Bl += z * sB;

    float c[2][8][4];
#pragma unroll
    for (int i = 0; i < 2; ++i)
#pragma unroll
        for (int j = 0; j < 8; ++j)
#pragma unroll
            for (int e = 0; e < 4; ++e) c[i][j][e] = 0.f;

    const int KS = K >> 5;

    cp_tile2(Ah, Al, m0, 0, K, sbase + 0,     tid);
    cp_tile2(Bh, Bl, n0, 0, K, sbase + 16384, tid);
    CP_COMMIT();

    const int a_r = lane & 15;
    const int a_c = lane >> 4;
    const int b_r = ((lane >> 4) << 3) + (lane & 7);
    const int b_c = (lane >> 3) & 1;

    for (int s = 0; s < KS; ++s) {
        const uint32_t sb = sbase + (s & 1) * STG_BYTES;
        if (s + 1 < KS) {
            const uint32_t nb = sbase + ((s + 1) & 1) * STG_BYTES;
            const int kof = (s + 1) * 32;
            cp_tile2(Ah, Al, m0, kof, K, nb + 0,     tid);
            cp_tile2(Bh, Bl, n0, kof, K, nb + 16384, tid);
            CP_COMMIT();
            CP_WAIT1();
        } else {
            CP_WAIT0();
        }
        __syncthreads();

#pragma unroll
        for (int kk = 0; kk < 2; ++kk) {
            uint32_t a_h[2][4], a_l[2][4];
#pragma unroll
            for (int mi = 0; mi < 2; ++mi) {
                const int row = mw * 32 + mi * 16 + a_r;
                const int ch = kk * 2 + a_c;
                const uint32_t base = sb + row * 128;
                LDMX4(a_h[mi], base + ((ch       ^ (row & 7)) << 4));
                LDMX4(a_l[mi], base + (((ch + 4) ^ (row & 7)) << 4));
            }
#pragma unroll
            for (int np = 0; np < 4; ++np) {
                const int n = nw * 64 + np * 16 + b_r;
                const int ch = kk * 2 + b_c;
                const uint32_t base = sb + 16384 + n * 128;
                uint32_t bhf[4], blf[4];
                LDMX4(bhf, base + ((ch       ^ (n & 7)) << 4));
                LDMX4(blf, base + (((ch + 4) ^ (n & 7)) << 4));
#pragma unroll
                for (int mi = 0; mi < 2; ++mi) {
                    MMA16816(c[mi][2*np+0], a_h[mi], &bhf[0]);
                    MMA16816(c[mi][2*np+0], a_h[mi], &blf[0]);
                    MMA16816(c[mi][2*np+0], a_l[mi], &bhf[0]);
                    MMA16816(c[mi][2*np+1], a_h[mi], &bhf[2]);
                    MMA16816(c[mi][2*np+1], a_h[mi], &blf[2]);
                    MMA16816(c[mi][2*np+1], a_l[mi], &bhf[2]);
                }
            }
        }
        __syncthreads();
    }

    // ---- epilogue ----
    if (MODE == 2) {
        // stage tile in smem, emit transposed bf16 hi/lo, coalesced.
        float (*T)[129] = (float(*)[129])smem;
        const int rl0 = mw * 32 + (lane >> 2);
        const int cl0 = nw * 64 + (lane & 3) * 2;
#pragma unroll
        for (int mi = 0; mi < 2; ++mi)
#pragma unroll
            for (int hf = 0; hf < 2; ++hf) {
                const int rl = rl0 + mi * 16 + hf * 8;
#pragma unroll
                for (int nj = 0; nj < 8; ++nj) {
                    const int cl = cl0 + nj * 8;
                    float v0 = c[mi][nj][hf * 2 + 0];
                    float v1 = c[mi][nj][hf * 2 + 1];
                    if (bias) { v0 += __ldg(&bias[n0 + cl]); v1 += __ldg(&bias[n0 + cl + 1]); }
                    T[rl][cl]     = v0;
                    T[rl][cl + 1] = v1;
                }
            }
        __syncthreads();
        const int f  = tid >> 1;           // local output row (= source col)
        const int t0 = (tid & 1) * 64;     // source-row half
        const int b   = m0 / rbatch;
        const int r0l = m0 % rbatch;
        __nv_bfloat16* dh = Chi + (size_t)b * sC + (size_t)(n0 + f) * ldc + r0l + t0;
        __nv_bfloat16* dl = Clo + (size_t)b * sC + (size_t)(n0 + f) * ldc + r0l + t0;
#pragma unroll
        for (int q = 0; q < 8; ++q) {
            uint32_t hw[4], lw[4];
#pragma unroll
            for (int p = 0; p < 4; ++p) {
                float f0 = T[t0 + q * 8 + 2 * p][f];
                float f1 = T[t0 + q * 8 + 2 * p + 1][f];
                split2pack(f0, f1, hw[p], lw[p]);
            }
            ((uint4*)(dh + q * 8))[0] = make_uint4(hw[0], hw[1], hw[2], hw[3]);
            ((uint4*)(dl + q * 8))[0] = make_uint4(lw[0], lw[1], lw[2], lw[3]);
        }
        return;
    }

    const int r_base = m0 + mw * 32 + (lane >> 2);
    const int c_base = n0 + nw * 64 + (lane & 3) * 2;
#pragma unroll
    for (int mi = 0; mi < 2; ++mi) {
#pragma unroll
        for (int hf = 0; hf < 2; ++hf) {
            const size_t row = (size_t)(r_base + mi * 16 + hf * 8);
#pragma unroll
            for (int nj = 0; nj < 8; ++nj) {
                const int col = c_base + nj * 8;
                float v0 = c[mi][nj][hf * 2 + 0];
                float v1 = c[mi][nj][hf * 2 + 1];
                if (bias) { v0 += __ldg(&bias[col]); v1 += __ldg(&bias[col + 1]); }
                if (MODE == 0) {
                    float2* dst = (float2*)(Cf + z * sC + row * ldc + col);
                    *dst = make_float2(v0, v1);
                } else {
                    uint32_t hw, lw;
                    split2pack(v0, v1, hw, lw);
                    *(uint32_t*)(Chi + z * sC + row * ldc + col) = hw;
                    *(uint32_t*)(Clo + z * sC + row * ldc + col) = lw;
                }
            }
        }
    }
}

// ------------------------------ aux kernels ---------------------------------
__global__ __launch_bounds__(256) void split_kernel(
    const float4* __restrict__ src, __nv_bfloat16* __restrict__ dh,
    __nv_bfloat16* __restrict__ dl, int n4)
{
    int i = blockIdx.x * 256 + threadIdx.x;
    if (i >= n4) return;
    float4 v = src[i];
    uint32_t hw0, lw0, hw1, lw1;
    split2pack(v.x, v.y, hw0, lw0);
    split2pack(v.z, v.w, hw1, lw1);
    ((uint2*)dh)[i] = make_uint2(hw0, hw1);
    ((uint2*)dl)[i] = make_uint2(lw0, lw1);
}

// dst[c][r] = split(src[r][c]); src [R,C] fp32, dst [C,R] bf16 hi/lo.
__global__ __launch_bounds__(256) void tsplit_kernel(
    const float* __restrict__ src, __nv_bfloat16* __restrict__ dh,
    __nv_bfloat16* __restrict__ dl, int R, int C, size_t sS, size_t sD)
{
    __shared__ float t[32][33];
    const size_t z = blockIdx.z;
    src += z * sS; dh += z * sD; dl += z * sD;
    const int c0 = blockIdx.x * 32, r0 = blockIdx.y * 32;
    const int tx = threadIdx.x, ty = threadIdx.y;
#pragma unroll
    for (int k = 0; k < 4; ++k)
        t[ty + 8*k][tx] = src[(size_t)(r0 + ty + 8*k) * C + c0 + tx];
    __syncthreads();
#pragma unroll
    for (int k = 0; k < 4; ++k) {
        float f = t[tx][ty + 8*k];
        __nv_bfloat16 h = __float2bfloat16_rn(f);
        size_t o = (size_t)(c0 + ty + 8*k) * R + r0 + tx;
        dh[o] = h;
        dl[o] = __float2bfloat16_rn(f - __bfloat162float(h));
    }
}

// bvo[f] = sum_c bv[c] * Wo[c][f]
__global__ __launch_bounds__(256) void bvo_kernel(
    const float* __restrict__ bv, const float* __restrict__ wo,
    float* __restrict__ bvo)
{
    int f = blockIdx.x * 256 + threadIdx.x;
    float s = 0.f;
    for (int c = 0; c < CH; ++c) s = fmaf(bv[c], wo[(size_t)c * CH + f], s);
    bvo[f] = s;
}

__global__ __launch_bounds__(256) void softmax_mask_split_kernel(
    const float* __restrict__ S, const float* __restrict__ masks,
    float* __restrict__ beta, __nv_bfloat16* __restrict__ bh,
    __nv_bfloat16* __restrict__ bl)
{
    const int row = blockIdx.x;
    const int b = row >> 8;
    const int n = threadIdx.x;
    __shared__ float red[256];

    const size_t idx = (size_t)row * NTOK + n;
    float v = S[idx];
    red[n] = v;
    __syncthreads();
#pragma unroll
    for (int s = 128; s > 0; s >>= 1) {
        if (n < s) red[n] = fmaxf(red[n], red[n + s]);
        __syncthreads();
    }
    const float mx = red[0];
    __syncthreads();
    const float e = expf(v - mx);
    red[n] = e;
    __syncthreads();
#pragma unroll
    for (int s = 128; s > 0; s >>= 1) {
        if (n < s) red[n] += red[n + s];
        __syncthreads();
    }
    const float r = e / red[0] * masks[b * NTOK + n];
    beta[idx] = r;
    __nv_bfloat16 h = __float2bfloat16_rn(r);
    bh[idx] = h;
    bl[idx] = __float2bfloat16_rn(r - __bfloat162float(h));
}

// ------------------------------ host ----------------------------------------
extern "C" void kernel_launch(void* const* d_in, const int* in_sizes, int n_in,
                              void* d_out, int out_size) {
    const float* x1    = (const float*)d_in[0];
    const float* x2    = (const float*)d_in[1];
    const float* masks = (const float*)d_in[2];
    const float* wq    = (const float*)d_in[3];
    const float* bq    = (const float*)d_in[4];
    const float* wk    = (const float*)d_in[5];
    const float* bk    = (const float*)d_in[6];
    const float* wv    = (const float*)d_in[7];
    const float* bv    = (const float*)d_in[8];
    const float* wo    = (const float*)d_in[9];
    const float* bo    = (const float*)d_in[10];

    float* out      = (float*)d_out;
    float* o_out    = out;
    float* beta_out = out + (size_t)MROWS * CH;

    __nv_bfloat16 *x1h, *x1l, *x2h, *x2l, *wqh, *wql, *wkh, *wkl, *wvh, *wvl,
                  *woh, *wol, *Qh, *Ql, *Kh, *Kl, *Wvoth, *Wvotl, *VWth, *VWtl, *bh, *bl;
    float *bvo, *Sf;
    cudaGetSymbolAddress((void**)&x1h, g_x1h); cudaGetSymbolAddress((void**)&x1l, g_x1l);
    cudaGetSymbolAddress((void**)&x2h, g_x2h); cudaGetSymbolAddress((void**)&x2l, g_x2l);
    cudaGetSymbolAddress((void**)&wqh, g_wqh); cudaGetSymbolAddress((void**)&wql, g_wql);
    cudaGetSymbolAddress((void**)&wkh, g_wkh); cudaGetSymbolAddress((void**)&wkl, g_wkl);
    cudaGetSymbolAddress((void**)&wvh, g_wvh); cudaGetSymbolAddress((void**)&wvl, g_wvl);
    cudaGetSymbolAddress((void**)&woh, g_woh); cudaGetSymbolAddress((void**)&wol, g_wol);
    cudaGetSymbolAddress((void**)&Qh,  g_Qh);  cudaGetSymbolAddress((void**)&Ql,  g_Ql);
    cudaGetSymbolAddress((void**)&Kh,  g_Kh);  cudaGetSymbolAddress((void**)&Kl,  g_Kl);
    cudaGetSymbolAddress((void**)&bvo, g_bvo);
    cudaGetSymbolAddress((void**)&Wvoth, g_Wvoth); cudaGetSymbolAddress((void**)&Wvotl, g_Wvotl);
    cudaGetSymbolAddress((void**)&VWth, g_VWth); cudaGetSymbolAddress((void**)&VWtl, g_VWtl);
    cudaGetSymbolAddress((void**)&Sf,  g_S);
    cudaGetSymbolAddress((void**)&bh,  g_bh);  cudaGetSymbolAddress((void**)&bl,  g_bl);

    cudaFuncSetAttribute(mma_gemm<0>, cudaFuncAttributeMaxDynamicSharedMemorySize, SMEM_BYTES);
    cudaFuncSetAttribute(mma_gemm<1>, cudaFuncAttributeMaxDynamicSharedMemorySize, SMEM_BYTES);
    cudaFuncSetAttribute(mma_gemm<2>, cudaFuncAttributeMaxDynamicSharedMemorySize, SMEM_BYTES_T);

    const dim3 T(256);
    const dim3 TT(32, 8);

    // splits / weight prep
    split_kernel<<<(MROWS*CH/4 + 255)/256, 256>>>((const float4*)x1, x1h, x1l, MROWS*CH/4);
    split_kernel<<<(MROWS*TC/4 + 255)/256, 256>>>((const float4*)x2, x2h, x2l, MROWS*TC/4);
    split_kernel<<<(TC*CH/4 + 255)/256, 256>>>((const float4*)wv, wvh, wvl, TC*CH/4);
    tsplit_kernel<<<dim3(FD/32, CH/32, 1), TT>>>(wq, wqh, wql, CH, FD, 0, 0);
    tsplit_kernel<<<dim3(FD/32, TC/32, 1), TT>>>(wk, wkh, wkl, TC, FD, 0, 0);
    tsplit_kernel<<<dim3(CH/32, CH/32, 1), TT>>>(wo, woh, wol, CH, CH, 0, 0);
    bvo_kernel<<<CH/256, 256>>>(bv, wo, bvo);

    // Wvo = Wv @ Wo  -> transposed hi/lo directly  (M=768, N=1024, K=1024)
    mma_gemm<2><<<dim3(CH/128, TC/128, 1), T, SMEM_BYTES_T>>>(
        wvh, wvl, woh, wol, nullptr, nullptr, Wvoth, Wvotl, CH, TC, 0, 0, 0, TC);

    // Q = x1 @ Wq + bq  -> hi/lo   (M=16384, N=512, K=1024)
    mma_gemm<1><<<dim3(FD/128, MROWS/128, 1), T, SMEM_BYTES>>>(
        x1h, x1l, wqh, wql, bq, nullptr, Qh, Ql, CH, FD, 0, 0, 0, 1);
    // K = x2 @ Wk + bk  -> hi/lo   (M=16384, N=512, K=768)
    mma_gemm<1><<<dim3(FD/128, MROWS/128, 1), T, SMEM_BYTES>>>(
        x2h, x2l, wkh, wkl, bk, nullptr, Kh, Kl, TC, FD, 0, 0, 0, 1);

    // VW = x2 @ Wvo + bvo -> per-batch transposed hi/lo directly
    // (M=16384, N=1024, K=768); out VWt[b][CH][NTOK]
    mma_gemm<2><<<dim3(CH/128, MROWS/128, 1), T, SMEM_BYTES_T>>>(
        x2h, x2l, Wvoth, Wvotl, bvo, nullptr, VWth, VWtl, TC, NTOK,
        0, 0, (size_t)CH*NTOK, NTOK);

    // S[b] = Q_b @ K_b^T -> fp32   (per-batch 256x256, K=512)
    mma_gemm<0><<<dim3(NTOK/128, HW/128, BATCH), T, SMEM_BYTES>>>(
        Qh, Ql, Kh, Kl, nullptr, Sf, nullptr, nullptr, FD, NTOK,
        (size_t)HW*FD, (size_t)NTOK*FD, (size_t)HW*NTOK, 1);

    // beta = softmax(S) * mask -> d_out + hi/lo
    softmax_mask_split_kernel<<<MROWS, 256>>>(Sf, masks, beta_out, bh, bl);

    // o[b] = beta_b @ VW_b + bo -> fp32 out   (per-batch 256x1024, K=256)
    mma_gemm<0><<<dim3(CH/128, HW/128, BATCH), T, SMEM_BYTES>>>(
        bh, bl, VWth, VWtl, bo, o_out, nullptr, nullptr, NTOK, CH,
        (size_t)HW*NTOK, (size_t)CH*NTOK, (size_t)HW*CH, 1);
}

// round 12
// speedup vs baseline: 1.3352x; 1.0971x over previous
#include <cuda_runtime.h>
#include <cuda_fp16.h>
#include <cstdint>
#include <cstddef>

#define BATCH 64
#define HW    256
#define CH    1024
#define NTOK  256
#define TC    768
#define FD    512
#define MROWS (BATCH*HW)   // 16384

#define SCALE_F   256.0f
#define INV_SQ    (1.0f/65536.0f)

// ------------------------------ scratch (device globals; no allocs) ---------
__device__ __align__(256) __half g_x1h[(size_t)MROWS*CH], g_x1l[(size_t)MROWS*CH];
__device__ __align__(256) __half g_x2h[(size_t)MROWS*TC], g_x2l[(size_t)MROWS*TC];
__device__ __align__(256) __half g_wqh[(size_t)FD*CH],  g_wql[(size_t)FD*CH];
__device__ __align__(256) __half g_wkh[(size_t)FD*TC],  g_wkl[(size_t)FD*TC];
__device__ __align__(256) __half g_wvh[(size_t)TC*CH],  g_wvl[(size_t)TC*CH];   // split of Wv [768,1024]
__device__ __align__(256) __half g_woh[(size_t)CH*CH],  g_wol[(size_t)CH*CH];   // Wo^T [f,c]
__device__ __align__(256) __half g_Qh[(size_t)MROWS*FD], g_Ql[(size_t)MROWS*FD];
__device__ __align__(256) __half g_Kh[(size_t)MROWS*FD], g_Kl[(size_t)MROWS*FD];
__device__ __align__(256) float  g_bvo[CH];                                     // bv@Wo
__device__ __align__(256) __half g_Wvoth[(size_t)CH*TC], g_Wvotl[(size_t)CH*TC];// (Wv@Wo)^T hi/lo [1024,768]
__device__ __align__(256) __half g_VWth[(size_t)MROWS*CH], g_VWtl[(size_t)MROWS*CH]; // [b][CH][NTOK]
__device__ __align__(256) float  g_S [(size_t)MROWS*NTOK];
__device__ __align__(256) __half g_bh[(size_t)MROWS*NTOK], g_bl[(size_t)MROWS*NTOK];

// ------------------------------ PTX helpers (all portable, sm_80+) ----------
__device__ __forceinline__ uint32_t smem_u32(const void* p) {
    uint32_t a;
    asm("{ .reg .u64 t; cvta.to.shared.u64 t, %1; cvt.u32.u64 %0, t; }" : "=r"(a) : "l"(p));
    return a;
}
#define CP_ASYNC16(dst, src) \
    asm volatile("cp.async.cg.shared.global [%0], [%1], 16;" :: "r"(dst), "l"(src))
#define CP_COMMIT() asm volatile("cp.async.commit_group;" ::: "memory")
#define CP_WAIT1()  asm volatile("cp.async.wait_group 1;" ::: "memory")
#define CP_WAIT0()  asm volatile("cp.async.wait_group 0;" ::: "memory")

#define LDMX4(r, addr)                                                      \
    asm volatile("ldmatrix.sync.aligned.m8n8.x4.shared.b16 {%0,%1,%2,%3}, [%4];" \
        : "=r"((r)[0]), "=r"((r)[1]), "=r"((r)[2]), "=r"((r)[3]) : "r"(addr))

#define MMA16816(c, a, b)                                                   \
    asm volatile("mma.sync.aligned.m16n8k16.row.col.f32.f16.f16.f32 "       \
        "{%0,%1,%2,%3}, {%4,%5,%6,%7}, {%8,%9}, {%0,%1,%2,%3};"             \
        : "+f"((c)[0]), "+f"((c)[1]), "+f"((c)[2]), "+f"((c)[3])            \
        : "r"((a)[0]), "r"((a)[1]), "r"((a)[2]), "r"((a)[3]),               \
          "r"((b)[0]), "r"((b)[1]))

// split f -> fp16 hi/lo of (f*256), packed pairs
__device__ __forceinline__ void split2pack(float f0, float f1, uint32_t& hw, uint32_t& lw) {
    float s0 = f0 * SCALE_F, s1 = f1 * SCALE_F;
    __half h0 = __float2half_rn(s0);
    __half h1 = __float2half_rn(s1);
    __half l0 = __float2half_rn(s0 - __half2float(h0));
    __half l1 = __float2half_rn(s1 - __half2float(h1));
    hw = (uint32_t)__half_as_ushort(h0) | ((uint32_t)__half_as_ushort(h1) << 16);
    lw = (uint32_t)__half_as_ushort(l0) | ((uint32_t)__half_as_ushort(l1) << 16);
}

// ------------------------------ GEMM ----------------------------------------
// Operands are fp16 hi/lo splits of (X*256); accumulator holds 65536*true.
// TERMS==3: AhBh + AhBl + AlBh (rel err ~2^-22). TERMS==2: AhBh + AhBl (~2^-12).
// MODE 0: fp32 row-major C (true value + bias).
// MODE 1: fp16 hi/lo row-major C (re-split of true+bias).
// MODE 2: fp16 hi/lo TRANSPOSED C via smem; ldc = out pitch, sC = batch stride,
//         rbatch = source rows per batch.
#define STG_BYTES 32768
#define SMEM_BYTES (2*STG_BYTES)
#define SMEM_BYTES_T (128*129*4)

__device__ __forceinline__ void cp_tile2(
    const __half* __restrict__ gh, const __half* __restrict__ gl,
    int row0, int kof, int pitch, uint32_t sdst, int tid)
{
#pragma unroll
    for (int i = 0; i < 2; ++i) {
        int u = tid + i * 256;
        int row = u >> 2;
        int c4 = u & 3;
        {
            int c = c4;
            uint32_t dst = sdst + row * 128 + ((c ^ (row & 7)) << 4);
            const void* src = gh + (size_t)(row0 + row) * pitch + kof + c4 * 8;
            CP_ASYNC16(dst, src);
        }
        {
            int c = c4 + 4;
            uint32_t dst = sdst + row * 128 + ((c ^ (row & 7)) << 4);
            const void* src = gl + (size_t)(row0 + row) * pitch + kof + c4 * 8;
            CP_ASYNC16(dst, src);
        }
    }
}

template <int MODE, int TERMS>
__global__ __launch_bounds__(256, 2) void mma_gemm(
    const __half* __restrict__ Ah, const __half* __restrict__ Al,
    const __half* __restrict__ Bh, const __half* __restrict__ Bl,
    const float* __restrict__ bias,
    float* __restrict__ Cf, __half* __restrict__ Chi, __half* __restrict__ Clo,
    int K, int ldc, size_t sA, size_t sB, size_t sC, int rbatch)
{
    extern __shared__ char smem[];
    const uint32_t sbase = smem_u32(smem);
    const int tid  = threadIdx.x;
    const int lane = tid & 31;
    const int wid  = tid >> 5;
    const int mw   = wid & 3;
    const int nw   = wid >> 2;
    const int m0 = blockIdx.y * 128;
    const int n0 = blockIdx.x * 128;
    const size_t z = blockIdx.z;
    Ah += z * sA; Al += z * sA;
    Bh += z * sB; Bl += z * sB;

    float c[2][8][4];
#pragma unroll
    for (int i = 0; i < 2; ++i)
#pragma unroll
        for (int j = 0; j < 8; ++j)
#pragma unroll
            for (int e = 0; e < 4; ++e) c[i][j][e] = 0.f;

    const int KS = K >> 5;

    cp_tile2(Ah, Al, m0, 0, K, sbase + 0,     tid);
    cp_tile2(Bh, Bl, n0, 0, K, sbase + 16384, tid);
    CP_COMMIT();

    const int a_r = lane & 15;
    const int a_c = lane >> 4;
    const int b_r = ((lane >> 4) << 3) + (lane & 7);
    const int b_c = (lane >> 3) & 1;

    for (int s = 0; s < KS; ++s) {
        const uint32_t sb = sbase + (s & 1) * STG_BYTES;
        if (s + 1 < KS) {
            const uint32_t nb = sbase + ((s + 1) & 1) * STG_BYTES;
            const int kof = (s + 1) * 32;
            cp_tile2(Ah, Al, m0, kof, K, nb + 0,     tid);
            cp_tile2(Bh, Bl, n0, kof, K, nb + 16384, tid);
            CP_COMMIT();
            CP_WAIT1();
        } else {
            CP_WAIT0();
        }
        __syncthreads();

#pragma unroll
        for (int kk = 0; kk < 2; ++kk) {
            uint32_t a_h[2][4], a_l[2][4];
#pragma unroll
            for (int mi = 0; mi < 2; ++mi) {
                const int row = mw * 32 + mi * 16 + a_r;
                const int ch = kk * 2 + a_c;
                const uint32_t base = sb + row * 128;
                LDMX4(a_h[mi], base + ((ch ^ (row & 7)) << 4));
                if (TERMS == 3) LDMX4(a_l[mi], base + (((ch + 4) ^ (row & 7)) << 4));
            }
#pragma unroll
            for (int np = 0; np < 4; ++np) {
                const int n = nw * 64 + np * 16 + b_r;
                const int ch = kk * 2 + b_c;
                const uint32_t base = sb + 16384 + n * 128;
                uint32_t bhf[4], blf[4];
                LDMX4(bhf, base + ((ch       ^ (n & 7)) << 4));
                LDMX4(blf, base + (((ch + 4) ^ (n & 7)) << 4));
#pragma unroll
                for (int mi = 0; mi < 2; ++mi) {
                    MMA16816(c[mi][2*np+0], a_h[mi], &bhf[0]);
                    MMA16816(c[mi][2*np+0], a_h[mi], &blf[0]);
                    if (TERMS == 3) MMA16816(c[mi][2*np+0], a_l[mi], &bhf[0]);
                    MMA16816(c[mi][2*np+1], a_h[mi], &bhf[2]);
                    MMA16816(c[mi][2*np+1], a_h[mi], &blf[2]);
                    if (TERMS == 3) MMA16816(c[mi][2*np+1], a_l[mi], &bhf[2]);
                }
            }
        }
        __syncthreads();
    }

    // ---- epilogue ----
    if (MODE == 2) {
        float (*T)[129] = (float(*)[129])smem;
        const int rl0 = mw * 32 + (lane >> 2);
        const int cl0 = nw * 64 + (lane & 3) * 2;
#pragma unroll
        for (int mi = 0; mi < 2; ++mi)
#pragma unroll
            for (int hf = 0; hf < 2; ++hf) {
                const int rl = rl0 + mi * 16 + hf * 8;
#pragma unroll
                for (int nj = 0; nj < 8; ++nj) {
                    const int cl = cl0 + nj * 8;
                    float v0 = c[mi][nj][hf * 2 + 0] * INV_SQ;
                    float v1 = c[mi][nj][hf * 2 + 1] * INV_SQ;
                    if (bias) { v0 += __ldg(&bias[n0 + cl]); v1 += __ldg(&bias[n0 + cl + 1]); }
                    T[rl][cl]     = v0;
                    T[rl][cl + 1] = v1;
                }
            }
        __syncthreads();
        const int f  = tid >> 1;
        const int t0 = (tid & 1) * 64;
        const int b   = m0 / rbatch;
        const int r0l = m0 % rbatch;
        __half* dh = Chi + (size_t)b * sC + (size_t)(n0 + f) * ldc + r0l + t0;
        __half* dl = Clo + (size_t)b * sC + (size_t)(n0 + f) * ldc + r0l + t0;
#pragma unroll
        for (int q = 0; q < 8; ++q) {
            uint32_t hw[4], lw[4];
#pragma unroll
            for (int p = 0; p < 4; ++p) {
                float f0 = T[t0 + q * 8 + 2 * p][f];
                float f1 = T[t0 + q * 8 + 2 * p + 1][f];
                split2pack(f0, f1, hw[p], lw[p]);
            }
            ((uint4*)(dh + q * 8))[0] = make_uint4(hw[0], hw[1], hw[2], hw[3]);
            ((uint4*)(dl + q * 8))[0] = make_uint4(lw[0], lw[1], lw[2], lw[3]);
        }
        return;
    }

    const int r_base = m0 + mw * 32 + (lane >> 2);
    const int c_base = n0 + nw * 64 + (lane & 3) * 2;
#pragma unroll
    for (int mi = 0; mi < 2; ++mi) {
#pragma unroll
        for (int hf = 0; hf < 2; ++hf) {
            const size_t row = (size_t)(r_base + mi * 16 + hf * 8);
#pragma unroll
            for (int nj = 0; nj < 8; ++nj) {
                const int col = c_base + nj * 8;
                float v0 = c[mi][nj][hf * 2 + 0] * INV_SQ;
                float v1 = c[mi][nj][hf * 2 + 1] * INV_SQ;
                if (bias) { v0 += __ldg(&bias[col]); v1 += __ldg(&bias[col + 1]); }
                if (MODE == 0) {
                    float2* dst = (float2*)(Cf + z * sC + row * ldc + col);
                    *dst = make_float2(v0, v1);
                } else {
                    uint32_t hw, lw;
                    split2pack(v0, v1, hw, lw);
                    *(uint32_t*)(Chi + z * sC + row * ldc + col) = hw;
                    *(uint32_t*)(Clo + z * sC + row * ldc + col) = lw;
                }
            }
        }
    }
}

// ------------------------------ aux kernels ---------------------------------
__global__ __launch_bounds__(256) void split_kernel(
    const float4* __restrict__ src, __half* __restrict__ dh,
    __half* __restrict__ dl, int n4)
{
    int i = blockIdx.x * 256 + threadIdx.x;
    if (i >= n4) return;
    float4 v = src[i];
    uint32_t hw0, lw0, hw1, lw1;
    split2pack(v.x, v.y, hw0, lw0);
    split2pack(v.z, v.w, hw1, lw1);
    ((uint2*)dh)[i] = make_uint2(hw0, hw1);
    ((uint2*)dl)[i] = make_uint2(lw0, lw1);
}

// dst[c][r] = split(src[r][c]); src [R,C] fp32, dst [C,R] fp16 hi/lo.
__global__ __launch_bounds__(256) void tsplit_kernel(
    const float* __restrict__ src, __half* __restrict__ dh,
    __half* __restrict__ dl, int R, int C, size_t sS, size_t sD)
{
    __shared__ float t[32][33];
    const size_t z = blockIdx.z;
    src += z * sS; dh += z * sD; dl += z * sD;
    const int c0 = blockIdx.x * 32, r0 = blockIdx.y * 32;
    const int tx = threadIdx.x, ty = threadIdx.y;
#pragma unroll
    for (int k = 0; k < 4; ++k)
        t[ty + 8*k][tx] = src[(size_t)(r0 + ty + 8*k) * C + c0 + tx];
    __syncthreads();
#pragma unroll
    for (int k = 0; k < 4; ++k) {
        float f = t[tx][ty + 8*k] * SCALE_F;
        __half h = __float2half_rn(f);
        size_t o = (size_t)(c0 + ty + 8*k) * R + r0 + tx;
        dh[o] = h;
        dl[o] = __float2half_rn(f - __half2float(h));
    }
}

// bvo[f] = sum_c bv[c] * Wo[c][f]
__global__ __launch_bounds__(256) void bvo_kernel(
    const float* __restrict__ bv, const float* __restrict__ wo,
    float* __restrict__ bvo)
{
    int f = blockIdx.x * 256 + threadIdx.x;
    float s = 0.f;
    for (int c = 0; c < CH; ++c) s = fmaf(bv[c], wo[(size_t)c * CH + f], s);
    bvo[f] = s;
}

__global__ __launch_bounds__(256) void softmax_mask_split_kernel(
    const float* __restrict__ S, const float* __restrict__ masks,
    float* __restrict__ beta, __half* __restrict__ bh,
    __half* __restrict__ bl)
{
    const int row = blockIdx.x;
    const int b = row >> 8;
    const int n = threadIdx.x;
    __shared__ float red[256];

    const size_t idx = (size_t)row * NTOK + n;
    float v = S[idx];
    red[n] = v;
    __syncthreads();
#pragma unroll
    for (int s = 128; s > 0; s >>= 1) {
        if (n < s) red[n] = fmaxf(red[n], red[n + s]);
        __syncthreads();
    }
    const float mx = red[0];
    __syncthreads();
    const float e = expf(v - mx);
    red[n] = e;
    __syncthreads();
#pragma unroll
    for (int s = 128; s > 0; s >>= 1) {
        if (n < s) red[n] += red[n + s];
        __syncthreads();
    }
    const float r = e / red[0] * masks[b * NTOK + n];
    beta[idx] = r;
    const float rs = r * SCALE_F;
    __half h = __float2half_rn(rs);
    bh[idx] = h;
    bl[idx] = __float2half_rn(rs - __half2float(h));
}

// ------------------------------ host ----------------------------------------
extern "C" void kernel_launch(void* const* d_in, const int* in_sizes, int n_in,
                              void* d_out, int out_size) {
    const float* x1    = (const float*)d_in[0];
    const float* x2    = (const float*)d_in[1];
    const float* masks = (const float*)d_in[2];
    const float* wq    = (const float*)d_in[3];
    const float* bq    = (const float*)d_in[4];
    const float* wk    = (const float*)d_in[5];
    const float* bk    = (const float*)d_in[6];
    const float* wv    = (const float*)d_in[7];
    const float* bv    = (const float*)d_in[8];
    const float* wo    = (const float*)d_in[9];
    const float* bo    = (const float*)d_in[10];

    float* out      = (float*)d_out;
    float* o_out    = out;
    float* beta_out = out + (size_t)MROWS * CH;

    __half *x1h, *x1l, *x2h, *x2l, *wqh, *wql, *wkh, *wkl, *wvh, *wvl,
           *woh, *wol, *Qh, *Ql, *Kh, *Kl, *Wvoth, *Wvotl, *VWth, *VWtl, *bh, *bl;
    float *bvo, *Sf;
    cudaGetSymbolAddress((void**)&x1h, g_x1h); cudaGetSymbolAddress((void**)&x1l, g_x1l);
    cudaGetSymbolAddress((void**)&x2h, g_x2h); cudaGetSymbolAddress((void**)&x2l, g_x2l);
    cudaGetSymbolAddress((void**)&wqh, g_wqh); cudaGetSymbolAddress((void**)&wql, g_wql);
    cudaGetSymbolAddress((void**)&wkh, g_wkh); cudaGetSymbolAddress((void**)&wkl, g_wkl);
    cudaGetSymbolAddress((void**)&wvh, g_wvh); cudaGetSymbolAddress((void**)&wvl, g_wvl);
    cudaGetSymbolAddress((void**)&woh, g_woh); cudaGetSymbolAddress((void**)&wol, g_wol);
    cudaGetSymbolAddress((void**)&Qh,  g_Qh);  cudaGetSymbolAddress((void**)&Ql,  g_Ql);
    cudaGetSymbolAddress((void**)&Kh,  g_Kh);  cudaGetSymbolAddress((void**)&Kl,  g_Kl);
    cudaGetSymbolAddress((void**)&bvo, g_bvo);
    cudaGetSymbolAddress((void**)&Wvoth, g_Wvoth); cudaGetSymbolAddress((void**)&Wvotl, g_Wvotl);
    cudaGetSymbolAddress((void**)&VWth, g_VWth); cudaGetSymbolAddress((void**)&VWtl, g_VWtl);
    cudaGetSymbolAddress((void**)&Sf,  g_S);
    cudaGetSymbolAddress((void**)&bh,  g_bh);  cudaGetSymbolAddress((void**)&bl,  g_bl);

    cudaFuncSetAttribute((const void*)mma_gemm<0,3>, cudaFuncAttributeMaxDynamicSharedMemorySize, SMEM_BYTES);
    cudaFuncSetAttribute((const void*)mma_gemm<0,2>, cudaFuncAttributeMaxDynamicSharedMemorySize, SMEM_BYTES);
    cudaFuncSetAttribute((const void*)mma_gemm<1,3>, cudaFuncAttributeMaxDynamicSharedMemorySize, SMEM_BYTES);
    cudaFuncSetAttribute((const void*)mma_gemm<2,3>, cudaFuncAttributeMaxDynamicSharedMemorySize, SMEM_BYTES_T);
    cudaFuncSetAttribute((const void*)mma_gemm<2,2>, cudaFuncAttributeMaxDynamicSharedMemorySize, SMEM_BYTES_T);

    const dim3 T(256);
    const dim3 TT(32, 8);

    // splits / weight prep
    split_kernel<<<(MROWS*CH/4 + 255)/256, 256>>>((const float4*)x1, x1h, x1l, MROWS*CH/4);
    split_kernel<<<(MROWS*TC/4 + 255)/256, 256>>>((const float4*)x2, x2h, x2l, MROWS*TC/4);
    split_kernel<<<(TC*CH/4 + 255)/256, 256>>>((const float4*)wv, wvh, wvl, TC*CH/4);
    tsplit_kernel<<<dim3(FD/32, CH/32, 1), TT>>>(wq, wqh, wql, CH, FD, 0, 0);
    tsplit_kernel<<<dim3(FD/32, TC/32, 1), TT>>>(wk, wkh, wkl, TC, FD, 0, 0);
    tsplit_kernel<<<dim3(CH/32, CH/32, 1), TT>>>(wo, woh, wol, CH, CH, 0, 0);
    bvo_kernel<<<CH/256, 256>>>(bv, wo, bvo);

    // Wvo = Wv @ Wo  -> transposed hi/lo  (M=768, N=1024, K=1024), 3-term
    mma_gemm<2,3><<<dim3(CH/128, TC/128, 1), T, SMEM_BYTES_T>>>(
        wvh, wvl, woh, wol, nullptr, nullptr, Wvoth, Wvotl, CH, TC, 0, 0, 0, TC);

    // Q = x1 @ Wq + bq  -> hi/lo  (3-term)
    mma_gemm<1,3><<<dim3(FD/128, MROWS/128, 1), T, SMEM_BYTES>>>(
        x1h, x1l, wqh, wql, bq, nullptr, Qh, Ql, CH, FD, 0, 0, 0, 1);
    // K = x2 @ Wk + bk  -> hi/lo  (3-term)
    mma_gemm<1,3><<<dim3(FD/128, MROWS/128, 1), T, SMEM_BYTES>>>(
        x2h, x2l, wkh, wkl, bk, nullptr, Kh, Kl, TC, FD, 0, 0, 0, 1);

    // VW = x2 @ Wvo + bvo -> per-batch transposed hi/lo  (2-term)
    mma_gemm<2,2><<<dim3(CH/128, MROWS/128, 1), T, SMEM_BYTES_T>>>(
        x2h, x2l, Wvoth, Wvotl, bvo, nullptr, VWth, VWtl, TC, NTOK,
        0, 0, (size_t)CH*NTOK, NTOK);

    // S[b] = Q_b @ K_b^T -> fp32  (3-term)
    mma_gemm<0,3><<<dim3(NTOK/128, HW/128, BATCH), T, SMEM_BYTES>>>(
        Qh, Ql, Kh, Kl, nullptr, Sf, nullptr, nullptr, FD, NTOK,
        (size_t)HW*FD, (size_t)NTOK*FD, (size_t)HW*NTOK, 1);

    // beta = softmax(S) * mask -> d_out + hi/lo
    softmax_mask_split_kernel<<<MROWS, 256>>>(Sf, masks, beta_out, bh, bl);

    // o[b] = beta_b @ VW_b + bo -> fp32 out  (2-term)
    mma_gemm<0,2><<<dim3(CH/128, HW/128, BATCH), T, SMEM_BYTES>>>(
        bh, bl, VWth, VWtl, bo, o_out, nullptr, nullptr, NTOK, CH,
        (size_t)HW*NTOK, (size_t)CH*NTOK, (size_t)HW*CH, 1);
}

// round 14
// speedup vs baseline: 1.5594x; 1.1679x over previous
#include <cuda_runtime.h>
#include <cuda_fp16.h>
#include <cstdint>
#include <cstddef>

#define BATCH 64
#define HW    256
#define CH    1024
#define NTOK  256
#define TC    768
#define FD    512
#define MROWS (BATCH*HW)   // 16384

#define SCALE_F   256.0f
#define INV_SQ    (1.0f/65536.0f)

// ------------------------------ scratch (device globals; no allocs) ---------
__device__ __align__(256) __half g_x1h[(size_t)MROWS*CH], g_x1l[(size_t)MROWS*CH];
__device__ __align__(256) __half g_x2h[(size_t)MROWS*TC], g_x2l[(size_t)MROWS*TC];
__device__ __align__(256) __half g_wqh[(size_t)FD*CH],  g_wql[(size_t)FD*CH];
__device__ __align__(256) __half g_wkh[(size_t)FD*TC],  g_wkl[(size_t)FD*TC];
__device__ __align__(256) __half g_wvh[(size_t)TC*CH],  g_wvl[(size_t)TC*CH];
__device__ __align__(256) __half g_woh[(size_t)CH*CH],  g_wol[(size_t)CH*CH];   // Wo^T [f,c]
__device__ __align__(256) __half g_Qh[(size_t)MROWS*FD], g_Ql[(size_t)MROWS*FD];
__device__ __align__(256) __half g_Kh[(size_t)MROWS*FD], g_Kl[(size_t)MROWS*FD];
__device__ __align__(256) float  g_bvo[CH];
__device__ __align__(256) __half g_Wvoth[(size_t)CH*TC], g_Wvotl[(size_t)CH*TC];// (Wv@Wo)^T hi/lo
__device__ __align__(256) __half g_VWth[(size_t)MROWS*CH], g_VWtl[(size_t)MROWS*CH]; // [b][CH][NTOK]
__device__ __align__(256) float  g_S [(size_t)MROWS*NTOK];
__device__ __align__(256) __half g_bh[(size_t)MROWS*NTOK], g_bl[(size_t)MROWS*NTOK];

// ------------------------------ PTX helpers ---------------------------------
__device__ __forceinline__ uint32_t smem_u32(const void* p) {
    uint32_t a;
    asm("{ .reg .u64 t; cvta.to.shared.u64 t, %1; cvt.u32.u64 %0, t; }" : "=r"(a) : "l"(p));
    return a;
}
#define CP_ASYNC16(dst, src) \
    asm volatile("cp.async.cg.shared.global [%0], [%1], 16;" :: "r"(dst), "l"(src))
#define CP_COMMIT() asm volatile("cp.async.commit_group;" ::: "memory")
#define CP_WAIT1()  asm volatile("cp.async.wait_group 1;" ::: "memory")
#define CP_WAIT0()  asm volatile("cp.async.wait_group 0;" ::: "memory")

#define LDMX4(r, addr)                                                      \
    asm volatile("ldmatrix.sync.aligned.m8n8.x4.shared.b16 {%0,%1,%2,%3}, [%4];" \
        : "=r"((r)[0]), "=r"((r)[1]), "=r"((r)[2]), "=r"((r)[3]) : "r"(addr))

#define MMA16816(c, a, b)                                                   \
    asm volatile("mma.sync.aligned.m16n8k16.row.col.f32.f16.f16.f32 "       \
        "{%0,%1,%2,%3}, {%4,%5,%6,%7}, {%8,%9}, {%0,%1,%2,%3};"             \
        : "+f"((c)[0]), "+f"((c)[1]), "+f"((c)[2]), "+f"((c)[3])            \
        : "r"((a)[0]), "r"((a)[1]), "r"((a)[2]), "r"((a)[3]),               \
          "r"((b)[0]), "r"((b)[1]))

// split f -> fp16 hi/lo of (f*256), packed pairs
__device__ __forceinline__ void split2pack(float f0, float f1, uint32_t& hw, uint32_t& lw) {
    float s0 = f0 * SCALE_F, s1 = f1 * SCALE_F;
    __half h0 = __float2half_rn(s0);
    __half h1 = __float2half_rn(s1);
    __half l0 = __float2half_rn(s0 - __half2float(h0));
    __half l1 = __float2half_rn(s1 - __half2float(h1));
    hw = (uint32_t)__half_as_ushort(h0) | ((uint32_t)__half_as_ushort(h1) << 16);
    lw = (uint32_t)__half_as_ushort(l0) | ((uint32_t)__half_as_ushort(l1) << 16);
}

// ------------------------------ GEMM ----------------------------------------
// Operands are fp16 hi/lo splits of (X*256); accumulator holds 65536*true.
// TERMS==3: AhBh + AhBl + AlBh.   TERMS==1: AhBh only (lo never loaded).
// MODE 0: fp32 row-major C.  MODE 1: fp16 hi/lo row-major C.
// MODE 2: fp16 hi/lo TRANSPOSED C via smem; ldc = out pitch, sC = batch stride,
//         rbatch = source rows per batch.
#define STG_BYTES 32768
#define SMEM_BYTES (2*STG_BYTES)
#define SMEM_BYTES_T (128*129*4)

template <bool LO>
__device__ __forceinline__ void cp_tile2(
    const __half* __restrict__ gh, const __half* __restrict__ gl,
    int row0, int kof, int pitch, uint32_t sdst, int tid)
{
#pragma unroll
    for (int i = 0; i < 2; ++i) {
        int u = tid + i * 256;
        int row = u >> 2;
        int c4 = u & 3;
        {
            int c = c4;
            uint32_t dst = sdst + row * 128 + ((c ^ (row & 7)) << 4);
            const void* src = gh + (size_t)(row0 + row) * pitch + kof + c4 * 8;
            CP_ASYNC16(dst, src);
        }
        if (LO) {
            int c = c4 + 4;
            uint32_t dst = sdst + row * 128 + ((c ^ (row & 7)) << 4);
            const void* src = gl + (size_t)(row0 + row) * pitch + kof + c4 * 8;
            CP_ASYNC16(dst, src);
        }
    }
}

template <int MODE, int TERMS>
__global__ __launch_bounds__(256, 2) void mma_gemm(
    const __half* __restrict__ Ah, const __half* __restrict__ Al,
    const __half* __restrict__ Bh, const __half* __restrict__ Bl,
    const float* __restrict__ bias,
    float* __restrict__ Cf, __half* __restrict__ Chi, __half* __restrict__ Clo,
    int K, int ldc, size_t sA, size_t sB, size_t sC, int rbatch)
{
    extern __shared__ char smem[];
    const uint32_t sbase = smem_u32(smem);
    const int tid  = threadIdx.x;
    const int lane = tid & 31;
    const int wid  = tid >> 5;
    const int mw   = wid & 3;
    const int nw   = wid >> 2;
    const int m0 = blockIdx.y * 128;
    const int n0 = blockIdx.x * 128;
    const size_t z = blockIdx.z;
    Ah += z * sA; Al += z * sA;
    Bh += z * sB; Bl += z * sB;

    float c[2][8][4];
#pragma unroll
    for (int i = 0; i < 2; ++i)
#pragma unroll
        for (int j = 0; j < 8; ++j)
#pragma unroll
            for (int e = 0; e < 4; ++e) c[i][j][e] = 0.f;

    const int KS = K >> 5;

    cp_tile2<(TERMS == 3)>(Ah, Al, m0, 0, K, sbase + 0,     tid);
    cp_tile2<(TERMS >= 2)>(Bh, Bl, n0, 0, K, sbase + 16384, tid);
    CP_COMMIT();

    const int a_r = lane & 15;
    const int a_c = lane >> 4;
    const int b_r = ((lane >> 4) << 3) + (lane & 7);
    const int b_c = (lane >> 3) & 1;

    for (int s = 0; s < KS; ++s) {
        const uint32_t sb = sbase + (s & 1) * STG_BYTES;
        if (s + 1 < KS) {
            const uint32_t nb = sbase + ((s + 1) & 1) * STG_BYTES;
            const int kof = (s + 1) * 32;
            cp_tile2<(TERMS == 3)>(Ah, Al, m0, kof, K, nb + 0,     tid);
            cp_tile2<(TERMS >= 2)>(Bh, Bl, n0, kof, K, nb + 16384, tid);
            CP_COMMIT();
            CP_WAIT1();
        } else {
            CP_WAIT0();
        }
        __syncthreads();

#pragma unroll
        for (int kk = 0; kk < 2; ++kk) {
            uint32_t a_h[2][4], a_l[2][4];
#pragma unroll
            for (int mi = 0; mi < 2; ++mi) {
                const int row = mw * 32 + mi * 16 + a_r;
                const int ch = kk * 2 + a_c;
                const uint32_t base = sb + row * 128;
                LDMX4(a_h[mi], base + ((ch ^ (row & 7)) << 4));
                if (TERMS == 3) LDMX4(a_l[mi], base + (((ch + 4) ^ (row & 7)) << 4));
            }
#pragma unroll
            for (int np = 0; np < 4; ++np) {
                const int n = nw * 64 + np * 16 + b_r;
                const int ch = kk * 2 + b_c;
                const uint32_t base = sb + 16384 + n * 128;
                uint32_t bhf[4], blf[4];
                LDMX4(bhf, base + ((ch ^ (n & 7)) << 4));
                if (TERMS >= 2) LDMX4(blf, base + (((ch + 4) ^ (n & 7)) << 4));
#pragma unroll
                for (int mi = 0; mi < 2; ++mi) {
                    MMA16816(c[mi][2*np+0], a_h[mi], &bhf[0]);
                    if (TERMS >= 2) MMA16816(c[mi][2*np+0], a_h[mi], &blf[0]);
                    if (TERMS == 3) MMA16816(c[mi][2*np+0], a_l[mi], &bhf[0]);
                    MMA16816(c[mi][2*np+1], a_h[mi], &bhf[2]);
                    if (TERMS >= 2) MMA16816(c[mi][2*np+1], a_h[mi], &blf[2]);
                    if (TERMS == 3) MMA16816(c[mi][2*np+1], a_l[mi], &bhf[2]);
                }
            }
        }
        __syncthreads();
    }

    // ---- epilogue ----
    if (MODE == 2) {
        float (*T)[129] = (float(*)[129])smem;
        const int rl0 = mw * 32 + (lane >> 2);
        const int cl0 = nw * 64 + (lane & 3) * 2;
#pragma unroll
        for (int mi = 0; mi < 2; ++mi)
#pragma unroll
            for (int hf = 0; hf < 2; ++hf) {
                const int rl = rl0 + mi * 16 + hf * 8;
#pragma unroll
                for (int nj = 0; nj < 8; ++nj) {
                    const int cl = cl0 + nj * 8;
                    float v0 = c[mi][nj][hf * 2 + 0] * INV_SQ;
                    float v1 = c[mi][nj][hf * 2 + 1] * INV_SQ;
                    if (bias) { v0 += __ldg(&bias[n0 + cl]); v1 += __ldg(&bias[n0 + cl + 1]); }
                    T[rl][cl]     = v0;
                    T[rl][cl + 1] = v1;
                }
            }
        __syncthreads();
        const int f  = tid >> 1;
        const int t0 = (tid & 1) * 64;
        const int b   = m0 / rbatch;
        const int r0l = m0 % rbatch;
        __half* dh = Chi + (size_t)b * sC + (size_t)(n0 + f) * ldc + r0l + t0;
        __half* dl = Clo + (size_t)b * sC + (size_t)(n0 + f) * ldc + r0l + t0;
#pragma unroll
        for (int q = 0; q < 8; ++q) {
            uint32_t hw[4], lw[4];
#pragma unroll
            for (int p = 0; p < 4; ++p) {
                float f0 = T[t0 + q * 8 + 2 * p][f];
                float f1 = T[t0 + q * 8 + 2 * p + 1][f];
                split2pack(f0, f1, hw[p], lw[p]);
            }
            ((uint4*)(dh + q * 8))[0] = make_uint4(hw[0], hw[1], hw[2], hw[3]);
            ((uint4*)(dl + q * 8))[0] = make_uint4(lw[0], lw[1], lw[2], lw[3]);
        }
        return;
    }

    const int r_base = m0 + mw * 32 + (lane >> 2);
    const int c_base = n0 + nw * 64 + (lane & 3) * 2;
#pragma unroll
    for (int mi = 0; mi < 2; ++mi) {
#pragma unroll
        for (int hf = 0; hf < 2; ++hf) {
            const size_t row = (size_t)(r_base + mi * 16 + hf * 8);
#pragma unroll
            for (int nj = 0; nj < 8; ++nj) {
                const int col = c_base + nj * 8;
                float v0 = c[mi][nj][hf * 2 + 0] * INV_SQ;
                float v1 = c[mi][nj][hf * 2 + 1] * INV_SQ;
                if (bias) { v0 += __ldg(&bias[col]); v1 += __ldg(&bias[col + 1]); }
                if (MODE == 0) {
                    float2* dst = (float2*)(Cf + z * sC + row * ldc + col);
                    *dst = make_float2(v0, v1);
                } else {
                    uint32_t hw, lw;
                    split2pack(v0, v1, hw, lw);
                    *(uint32_t*)(Chi + z * sC + row * ldc + col) = hw;
                    *(uint32_t*)(Clo + z * sC + row * ldc + col) = lw;
                }
            }
        }
    }
}

// ------------------------------ aux kernels ---------------------------------
__global__ __launch_bounds__(256) void split_kernel(
    const float4* __restrict__ src, __half* __restrict__ dh,
    __half* __restrict__ dl, int n4)
{
    int i = blockIdx.x * 256 + threadIdx.x;
    if (i >= n4) return;
    float4 v = src[i];
    uint32_t hw0, lw0, hw1, lw1;
    split2pack(v.x, v.y, hw0, lw0);
    split2pack(v.z, v.w, hw1, lw1);
    ((uint2*)dh)[i] = make_uint2(hw0, hw1);
    ((uint2*)dl)[i] = make_uint2(lw0, lw1);
}

// dst[c][r] = split(src[r][c]); src [R,C] fp32, dst [C,R] fp16 hi/lo.
__global__ __launch_bounds__(256) void tsplit_kernel(
    const float* __restrict__ src, __half* __restrict__ dh,
    __half* __restrict__ dl, int R, int C, size_t sS, size_t sD)
{
    __shared__ float t[32][33];
    const size_t z = blockIdx.z;
    src += z * sS; dh += z * sD; dl += z * sD;
    const int c0 = blockIdx.x * 32, r0 = blockIdx.y * 32;
    const int tx = threadIdx.x, ty = threadIdx.y;
#pragma unroll
    for (int k = 0; k < 4; ++k)
        t[ty + 8*k][tx] = src[(size_t)(r0 + ty + 8*k) * C + c0 + tx];
    __syncthreads();
#pragma unroll
    for (int k = 0; k < 4; ++k) {
        float f = t[tx][ty + 8*k] * SCALE_F;
        __half h = __float2half_rn(f);
        size_t o = (size_t)(c0 + ty + 8*k) * R + r0 + tx;
        dh[o] = h;
        dl[o] = __float2half_rn(f - __half2float(h));
    }
}

// bvo[f] = sum_c bv[c] * Wo[c][f]
__global__ __launch_bounds__(256) void bvo_kernel(
    const float* __restrict__ bv, const float* __restrict__ wo,
    float* __restrict__ bvo)
{
    int f = blockIdx.x * 256 + threadIdx.x;
    float s = 0.f;
    for (int c = 0; c < CH; ++c) s = fmaf(bv[c], wo[(size_t)c * CH + f], s);
    bvo[f] = s;
}

__global__ __launch_bounds__(256) void softmax_mask_split_kernel(
    const float* __restrict__ S, const float* __restrict__ masks,
    float* __restrict__ beta, __half* __restrict__ bh,
    __half* __restrict__ bl)
{
    const int row = blockIdx.x;
    const int b = row >> 8;
    const int n = threadIdx.x;
    __shared__ float red[256];

    const size_t idx = (size_t)row * NTOK + n;
    float v = S[idx];
    red[n] = v;
    __syncthreads();
#pragma unroll
    for (int s = 128; s > 0; s >>= 1) {
        if (n < s) red[n] = fmaxf(red[n], red[n + s]);
        __syncthreads();
    }
    const float mx = red[0];
    __syncthreads();
    const float e = expf(v - mx);
    red[n] = e;
    __syncthreads();
#pragma unroll
    for (int s = 128; s > 0; s >>= 1) {
        if (n < s) red[n] += red[n + s];
        __syncthreads();
    }
    const float r = e / red[0] * masks[b * NTOK + n];
    beta[idx] = r;
    const float rs = r * SCALE_F;
    __half h = __float2half_rn(rs);
    bh[idx] = h;
    bl[idx] = __float2half_rn(rs - __half2float(h));
}

// ------------------------------ host ----------------------------------------
extern "C" void kernel_launch(void* const* d_in, const int* in_sizes, int n_in,
                              void* d_out, int out_size) {
    const float* x1    = (const float*)d_in[0];
    const float* x2    = (const float*)d_in[1];
    const float* masks = (const float*)d_in[2];
    const float* wq    = (const float*)d_in[3];
    const float* bq    = (const float*)d_in[4];
    const float* wk    = (const float*)d_in[5];
    const float* bk    = (const float*)d_in[6];
    const float* wv    = (const float*)d_in[7];
    const float* bv    = (const float*)d_in[8];
    const float* wo    = (const float*)d_in[9];
    const float* bo    = (const float*)d_in[10];

    float* out      = (float*)d_out;
    float* o_out    = out;
    float* beta_out = out + (size_t)MROWS * CH;

    __half *x1h, *x1l, *x2h, *x2l, *wqh, *wql, *wkh, *wkl, *wvh, *wvl,
           *woh, *wol, *Qh, *Ql, *Kh, *Kl, *Wvoth, *Wvotl, *VWth, *VWtl, *bh, *bl;
    float *bvo, *Sf;
    cudaGetSymbolAddress((void**)&x1h, g_x1h); cudaGetSymbolAddress((void**)&x1l, g_x1l);
    cudaGetSymbolAddress((void**)&x2h, g_x2h); cudaGetSymbolAddress((void**)&x2l, g_x2l);
    cudaGetSymbolAddress((void**)&wqh, g_wqh); cudaGetSymbolAddress((void**)&wql, g_wql);
    cudaGetSymbolAddress((void**)&wkh, g_wkh); cudaGetSymbolAddress((void**)&wkl, g_wkl);
    cudaGetSymbolAddress((void**)&wvh, g_wvh); cudaGetSymbolAddress((void**)&wvl, g_wvl);
    cudaGetSymbolAddress((void**)&woh, g_woh); cudaGetSymbolAddress((void**)&wol, g_wol);
    cudaGetSymbolAddress((void**)&Qh,  g_Qh);  cudaGetSymbolAddress((void**)&Ql,  g_Ql);
    cudaGetSymbolAddress((void**)&Kh,  g_Kh);  cudaGetSymbolAddress((void**)&Kl,  g_Kl);
    cudaGetSymbolAddress((void**)&bvo, g_bvo);
    cudaGetSymbolAddress((void**)&Wvoth, g_Wvoth); cudaGetSymbolAddress((void**)&Wvotl, g_Wvotl);
    cudaGetSymbolAddress((void**)&VWth, g_VWth); cudaGetSymbolAddress((void**)&VWtl, g_VWtl);
    cudaGetSymbolAddress((void**)&Sf,  g_S);
    cudaGetSymbolAddress((void**)&bh,  g_bh);  cudaGetSymbolAddress((void**)&bl,  g_bl);

    cudaFuncSetAttribute((const void*)mma_gemm<0,3>, cudaFuncAttributeMaxDynamicSharedMemorySize, SMEM_BYTES);
    cudaFuncSetAttribute((const void*)mma_gemm<1,3>, cudaFuncAttributeMaxDynamicSharedMemorySize, SMEM_BYTES);
    cudaFuncSetAttribute((const void*)mma_gemm<0,1>, cudaFuncAttributeMaxDynamicSharedMemorySize, SMEM_BYTES);
    cudaFuncSetAttribute((const void*)mma_gemm<2,1>, cudaFuncAttributeMaxDynamicSharedMemorySize, SMEM_BYTES_T);

    const dim3 T(256);
    const dim3 TT(32, 8);

    // splits / weight prep
    split_kernel<<<(MROWS*CH/4 + 255)/256, 256>>>((const float4*)x1, x1h, x1l, MROWS*CH/4);
    split_kernel<<<(MROWS*TC/4 + 255)/256, 256>>>((const float4*)x2, x2h, x2l, MROWS*TC/4);
    split_kernel<<<(TC*CH/4 + 255)/256, 256>>>((const float4*)wv, wvh, wvl, TC*CH/4);
    tsplit_kernel<<<dim3(FD/32, CH/32, 1), TT>>>(wq, wqh, wql, CH, FD, 0, 0);
    tsplit_kernel<<<dim3(FD/32, TC/32, 1), TT>>>(wk, wkh, wkl, TC, FD, 0, 0);
    tsplit_kernel<<<dim3(CH/32, CH/32, 1), TT>>>(wo, woh, wol, CH, CH, 0, 0);
    bvo_kernel<<<CH/256, 256>>>(bv, wo, bvo);

    // Wvo = Wv @ Wo  -> transposed hi/lo  (M=768, N=1024, K=1024), 1-term
    mma_gemm<2,1><<<dim3(CH/128, TC/128, 1), T, SMEM_BYTES_T>>>(
        wvh, wvl, woh, wol, nullptr, nullptr, Wvoth, Wvotl, CH, TC, 0, 0, 0, TC);

    // Q = x1 @ Wq + bq  -> hi/lo   (3-term)
    mma_gemm<1,3><<<dim3(FD/128, MROWS/128, 1), T, SMEM_BYTES>>>(
        x1h, x1l, wqh, wql, bq, nullptr, Qh, Ql, CH, FD, 0, 0, 0, 1);
    // K = x2 @ Wk + bk  -> hi/lo   (3-term)
    mma_gemm<1,3><<<dim3(FD/128, MROWS/128, 1), T, SMEM_BYTES>>>(
        x2h, x2l, wkh, wkl, bk, nullptr, Kh, Kl, TC, FD, 0, 0, 0, 1);

    // VW = x2 @ Wvo + bvo -> per-batch transposed hi/lo  (1-term)
    mma_gemm<2,1><<<dim3(CH/128, MROWS/128, 1), T, SMEM_BYTES_T>>>(
        x2h, x2l, Wvoth, Wvotl, bvo, nullptr, VWth, VWtl, TC, NTOK,
        0, 0, (size_t)CH*NTOK, NTOK);

    // S[b] = Q_b @ K_b^T -> fp32   (3-term)
    mma_gemm<0,3><<<dim3(NTOK/128, HW/128, BATCH), T, SMEM_BYTES>>>(
        Qh, Ql, Kh, Kl, nullptr, Sf, nullptr, nullptr, FD, NTOK,
        (size_t)HW*FD, (size_t)NTOK*FD, (size_t)HW*NTOK, 1);

    // beta = softmax(S) * mask -> d_out + hi/lo
    softmax_mask_split_kernel<<<MROWS, 256>>>(Sf, masks, beta_out, bh, bl);

    // o[b] = beta_b @ VW_b + bo -> fp32 out   (1-term)
    mma_gemm<0,1><<<dim3(CH/128, HW/128, BATCH), T, SMEM_BYTES>>>(
        bh, bl, VWth, VWtl, bo, o_out, nullptr, nullptr, NTOK, CH,
        (size_t)HW*NTOK, (size_t)CH*NTOK, (size_t)HW*CH, 1);
}